// round 8
// baseline (speedup 1.0000x reference)
#include <cuda_runtime.h>
#include <cuda_fp16.h>
#include <cstdint>

#define B_    64
#define N_    2048
#define JD_   512
#define EPS_  1e-8f
#define SROW2 72    // smem row stride in halves (144 B): conflict-free frag stores

// Scratch (device globals: allocation-free rule)
__device__ __half g_u[(size_t)B_ * N_ * JD_];        // 134 MB u[b][i][jd] fp16
__device__ float  g_part1[(size_t)128 * B_ * JD_];   // s1 partials (128 chunks)
__device__ float  g_part2[(size_t)16 * B_ * JD_];    // 16-chunk partials (s1/s2/s3)
__device__ float  g_v[2][B_ * JD_];                  // v1, (v1+v2)

__device__ __forceinline__ uint32_t packh2(float a, float b) {
    __half2 h = __floats2half2_rn(a, b);
    return *(uint32_t*)&h;
}
__device__ __forceinline__ void mma16816(float& d0, float& d1, float& d2, float& d3,
        uint32_t a0, uint32_t a1, uint32_t a2, uint32_t a3,
        uint32_t b0, uint32_t b1) {
    asm volatile(
        "mma.sync.aligned.m16n8k16.row.col.f32.f16.f16.f32 "
        "{%0,%1,%2,%3}, {%4,%5,%6,%7}, {%8,%9}, {%10,%11,%12,%13};\n"
        : "=f"(d0), "=f"(d1), "=f"(d2), "=f"(d3)
        : "r"(a0), "r"(a1), "r"(a2), "r"(a3), "r"(b0), "r"(b1),
          "f"(0.f), "f"(0.f), "f"(0.f), "f"(0.f));
}

// ---------------------------------------------------------------------------
// k_u: tensor-core einsum -> u (fp16, coalesced via smem transpose) + fused
// pass-1 partials (uniform c = 1/32, fp32 acc).
// Grid (128 ic, 2 bh), 512 thr = 16 warps; warp = (mt: 16 b) x (jdr: 64 jd).
// acc[8][4] = 32 regs -> 2 CTAs/SM (vs 1 before): 2x warps in flight.
// ---------------------------------------------------------------------------
__global__ __launch_bounds__(512, 2) void k_u(const float* __restrict__ x,
                                              const float* __restrict__ w) {
    extern __shared__ __half us[];       // 16 warps * 16 rows * SROW2 halves
    const int ic   = blockIdx.x;
    const int bh   = blockIdx.y;
    const int t    = threadIdx.x;
    const int wid  = t >> 5;
    const int lane = t & 31;
    const int g    = lane >> 2;
    const int tg   = lane & 3;
    const int mt   = wid & 1;
    const int jdr  = wid >> 1;           // 0..7
    const int jd0  = jdr * 64;
    const int row0 = bh * 32 + mt * 16 + g;
    const int row1 = row0 + 8;
    __half* usw = us + wid * 16 * SROW2; // this warp's 16x64 tile

    float acc[8][4];
#pragma unroll
    for (int q = 0; q < 8; q++)
#pragma unroll
        for (int r = 0; r < 4; r++) acc[q][r] = 0.f;

    for (int k = 0; k < 16; k++) {
        const int i = ic * 16 + k;

        // A fragment from fp32 x
        const float* xp0 = x + ((size_t)row0 * N_ + i) * 16 + 2 * tg;
        const float* xp1 = x + ((size_t)row1 * N_ + i) * 16 + 2 * tg;
        float2 f0 = *(const float2*)xp0;
        float2 f1 = *(const float2*)xp1;
        float2 f2 = *(const float2*)(xp0 + 8);
        float2 f3 = *(const float2*)(xp1 + 8);
        uint32_t A0 = packh2(f0.x, f0.y);
        uint32_t A1 = packh2(f1.x, f1.y);
        uint32_t A2 = packh2(f2.x, f2.y);
        uint32_t A3 = packh2(f3.x, f3.y);

#pragma unroll
        for (int q = 0; q < 8; q++) {
            const int col = jd0 + q * 8 + g;
            const float* wp = w + ((size_t)i * JD_ + col) * 16 + 2 * tg;
            float2 w0 = *(const float2*)wp;
            float2 w1 = *(const float2*)(wp + 8);
            uint32_t Bb0 = packh2(w0.x, w0.y);
            uint32_t Bb1 = packh2(w1.x, w1.y);

            float d0, d1, d2, d3;
            mma16816(d0, d1, d2, d3, A0, A1, A2, A3, Bb0, Bb1);
            acc[q][0] += d0; acc[q][1] += d1;
            acc[q][2] += d2; acc[q][3] += d3;

            // stage fragments (bank-clean: word addr = g*36 + q*4 + tg)
            *(uint32_t*)(usw + g * SROW2       + q * 8 + 2 * tg) = packh2(d0, d1);
            *(uint32_t*)(usw + (g + 8) * SROW2 + q * 8 + 2 * tg) = packh2(d2, d3);
        }
        __syncwarp();

        // coalesced copy-out: 16 rows x 128 B -> u[b][i][jd0..jd0+64)
#pragma unroll
        for (int it = 0; it < 4; it++) {
            const int r   = it * 4 + (lane >> 3);
            const int off = lane & 7;
            uint4 v = *(const uint4*)(usw + r * SROW2 + off * 8);
            *(uint4*)(g_u + ((size_t)(bh * 32 + mt * 16 + r) * N_ + i) * JD_
                      + jd0 + off * 8) = v;
        }
        __syncwarp();
    }

    // s1 partials: g_part1[ic][b][jd], scaled by 1/32
    float* pb = g_part1 + ((size_t)ic * B_ + row0) * JD_;
    const float cinv = 1.0f / 32.0f;
#pragma unroll
    for (int q = 0; q < 8; q++) {
        const int col = jd0 + q * 8 + 2 * tg;
        *(float2*)(pb + col)           = make_float2(acc[q][0] * cinv, acc[q][1] * cinv);
        *(float2*)(pb + 8 * JD_ + col) = make_float2(acc[q][2] * cinv, acc[q][3] * cinv);
    }
}

// ---------------------------------------------------------------------------
// Stage A of s1 reduce: 128 chunks -> 16 (high parallelism, 524288 threads).
// ---------------------------------------------------------------------------
__global__ void k_red1() {
    const int gidx = blockIdx.x * 256 + threadIdx.x;   // 2048 CTAs * 256
    const int grp  = gidx >> 15;                       // 0..15 (B_*JD_ = 32768)
    const int idx  = gidx & 32767;
    const float* p = g_part1 + (size_t)grp * 8 * (B_ * JD_) + idx;
    float s = 0.f;
#pragma unroll
    for (int c = 0; c < 8; c++)
        s += p[(size_t)c * B_ * JD_];
    g_part2[(size_t)grp * (B_ * JD_) + idx] = s;
}

// ---------------------------------------------------------------------------
// Routing sweep over fp16 u with depth-2 software prefetch.
// Grid (16, 64), 256 thr = 8 warps, warp handles 16 i, lane = j.
// Logit dot in half2; c*u accumulate in fp32. Writes g_part2[ic][b][jd].
// ---------------------------------------------------------------------------
__global__ __launch_bounds__(256, 3) void k_pass(int vIdx) {
    const int b    = blockIdx.y;
    const int ic   = blockIdx.x;
    const int t    = threadIdx.x;
    const int warp = t >> 5;
    const int j    = t & 31;

    __shared__ float vs[JD_];
    __shared__ float ss[8][JD_];

    for (int idx = t; idx < JD_; idx += 256)
        vs[idx] = g_v[vIdx][b * JD_ + idx];
    __syncthreads();

    __half2 vj2[8];
#pragma unroll
    for (int q = 0; q < 8; q++)
        vj2[q] = __floats2half2_rn(vs[j * 16 + 2 * q], vs[j * 16 + 2 * q + 1]);

    float acc[16];
#pragma unroll
    for (int d = 0; d < 16; d++) acc[d] = 0.f;

    const int ibase = ic * 128 + warp * 16;
    const uint4* ub = (const uint4*)(g_u + ((size_t)b * N_ + ibase) * JD_) + j * 2;

    uint4 p0 = __ldcs(ub);
    uint4 p1 = __ldcs(ub + 1);
    uint4 n0 = __ldcs(ub + 64);
    uint4 n1 = __ldcs(ub + 65);
    for (int k = 0; k < 16; k++) {
        // prefetch i+2 (clamped): 3 i-rows in flight
        const int kn = (k < 14) ? k + 2 : 15;
        uint4 m0 = __ldcs(ub + (size_t)kn * 64);
        uint4 m1 = __ldcs(ub + (size_t)kn * 64 + 1);

        // logit in half2
        const __half2* u2a = (const __half2*)&p0;
        const __half2* u2b = (const __half2*)&p1;
        __half2 h = __hmul2(u2a[0], vj2[0]);
#pragma unroll
        for (int q = 1; q < 4; q++) h = __hfma2(u2a[q], vj2[q], h);
#pragma unroll
        for (int q = 0; q < 4; q++) h = __hfma2(u2b[q], vj2[4 + q], h);
        float bl = __low2float(h) + __high2float(h);

        // softmax over 32 j-lanes
        float m = bl;
#pragma unroll
        for (int o = 16; o > 0; o >>= 1)
            m = fmaxf(m, __shfl_xor_sync(0xffffffffu, m, o));
        float ex = __expf(bl - m);
        float sum = ex;
#pragma unroll
        for (int o = 16; o > 0; o >>= 1)
            sum += __shfl_xor_sync(0xffffffffu, sum, o);
        const float c = ex / sum;

        // acc += c * u (fp32 unpack)
#pragma unroll
        for (int q = 0; q < 4; q++) {
            float2 ua = __half22float2(u2a[q]);
            float2 uc = __half22float2(u2b[q]);
            acc[2*q]     += c * ua.x;
            acc[2*q+1]   += c * ua.y;
            acc[8+2*q]   += c * uc.x;
            acc[8+2*q+1] += c * uc.y;
        }

        p0 = n0; p1 = n1;
        n0 = m0; n1 = m1;
    }

#pragma unroll
    for (int d = 0; d < 16; d++) ss[warp][d * 32 + j] = acc[d];
    __syncthreads();

    for (int idx = t; idx < JD_; idx += 256) {
        int d = idx >> 5, jj = idx & 31;
        float r = 0.f;
#pragma unroll
        for (int wi = 0; wi < 8; wi++) r += ss[wi][idx];
        g_part2[((size_t)ic * B_ + b) * JD_ + jj * 16 + d] = r;
    }
}

// ---------------------------------------------------------------------------
// Reduce g_part2 over 16 chunks, then squash.
// mode 0: g_v[0] = squash_J(s)             (v1)
// mode 1: g_v[1] = squash_J(s) + g_v[0]    (v1 + v2, additive logits)
// mode 2: out    = squash_D(s)
// ---------------------------------------------------------------------------
__global__ void k_squash(int mode, float* __restrict__ out) {
    const int b = blockIdx.x;
    const int t = threadIdx.x;     // t = j*16 + d
    const float* p = g_part2 + (size_t)b * JD_ + t;
    float s = 0.f;
#pragma unroll
    for (int ic = 0; ic < 16; ic++)
        s += p[(size_t)ic * B_ * JD_];

    if (mode == 2) {
        float q = s * s;
#pragma unroll
        for (int o = 1; o < 16; o <<= 1)   // 16 consecutive lanes = same j
            q += __shfl_xor_sync(0xffffffffu, q, o);
        out[b * JD_ + t] = s * (q / (1.f + q)) * rsqrtf(q + EPS_);
        return;
    }

    __shared__ float sq[16];
    if (t < 16) sq[t] = 0.f;
    __syncthreads();
    atomicAdd(&sq[t & 15], s * s);
    __syncthreads();
    float q = sq[t & 15];
    float v = s * (q / (1.f + q)) * rsqrtf(q + EPS_);
    if (mode == 0) g_v[0][b * JD_ + t] = v;
    else           g_v[1][b * JD_ + t] = v + g_v[0][b * JD_ + t];
}

// ---------------------------------------------------------------------------
extern "C" void kernel_launch(void* const* d_in, const int* in_sizes, int n_in,
                              void* d_out, int out_size) {
    const float* x = (const float*)d_in[0];
    const float* w = (const float*)d_in[1];
    if (in_sizes[0] != B_ * N_ * 16) {       // defensive input-order check
        x = (const float*)d_in[1];
        w = (const float*)d_in[0];
    }

    const int smemB = 16 * 16 * SROW2 * 2;   // 36864 B (2 CTAs/SM fit)
    cudaFuncSetAttribute(k_u, cudaFuncAttributeMaxDynamicSharedMemorySize, smemB);

    dim3 ug(128, 2);
    k_u<<<ug, 512, smemB>>>(x, w);               // u fp16 + s1 partials (128 chunks)
    k_red1<<<2048, 256>>>();                     // s1: 128 -> 16 chunks
    k_squash<<<B_, JD_>>>(0, nullptr);           // v1 = squash_J(s1)
    dim3 pg(16, B_);
    k_pass<<<pg, 256>>>(0);                      // iter 2: softmax(u.v1) -> s2
    k_squash<<<B_, JD_>>>(1, nullptr);           // vsum = squash_J(s2) + v1
    k_pass<<<pg, 256>>>(1);                      // final: softmax(u.vsum) -> s3
    k_squash<<<B_, JD_>>>(2, (float*)d_out);     // out = squash_D(s3)
}

// round 9
// speedup vs baseline: 1.0901x; 1.0901x over previous
#include <cuda_runtime.h>
#include <cuda_fp16.h>
#include <cstdint>

#define B_    64
#define N_    2048
#define JD_   512
#define EPS_  1e-8f
#define SROW  136   // smem row stride in halves (272 B): conflict-free frag stores

// Scratch (device globals: allocation-free rule)
__device__ __half g_u[(size_t)B_ * N_ * JD_];        // 134 MB u[b][i][jd] fp16
__device__ float  g_part1[(size_t)128 * B_ * JD_];   // s1 partials (128 chunks)
__device__ float  g_part2[(size_t)16 * B_ * JD_];    // 16-chunk partials (s1/s2/s3)
__device__ float  g_v[2][B_ * JD_];                  // v1, (v1+v2)

__device__ __forceinline__ uint32_t packh2(float a, float b) {
    __half2 h = __floats2half2_rn(a, b);
    return *(uint32_t*)&h;
}
__device__ __forceinline__ void mma16816(float& d0, float& d1, float& d2, float& d3,
        uint32_t a0, uint32_t a1, uint32_t a2, uint32_t a3,
        uint32_t b0, uint32_t b1) {
    asm volatile(
        "mma.sync.aligned.m16n8k16.row.col.f32.f16.f16.f32 "
        "{%0,%1,%2,%3}, {%4,%5,%6,%7}, {%8,%9}, {%10,%11,%12,%13};\n"
        : "=f"(d0), "=f"(d1), "=f"(d2), "=f"(d3)
        : "r"(a0), "r"(a1), "r"(a2), "r"(a3), "r"(b0), "r"(b1),
          "f"(0.f), "f"(0.f), "f"(0.f), "f"(0.f));
}

// ---------------------------------------------------------------------------
// k_u (round-5/7 proven config): tensor-core einsum -> u (fp16, coalesced via
// smem transpose) + fused pass-1 partials (uniform c = 1/32, fp32 acc).
// Grid 128 (16 i each), 512 thr = 16 warps; warp = (mt: 16 b) x (jdr: 128 jd).
// ---------------------------------------------------------------------------
__global__ __launch_bounds__(512, 1) void k_u(const float* __restrict__ x,
                                              const float* __restrict__ w) {
    extern __shared__ __half us[];       // 16 warps * 16 rows * SROW halves
    const int ic   = blockIdx.x;
    const int t    = threadIdx.x;
    const int wid  = t >> 5;
    const int lane = t & 31;
    const int g    = lane >> 2;
    const int tg   = lane & 3;
    const int mt   = wid & 3;
    const int jdr  = wid >> 2;
    const int jd0  = jdr * 128;
    const int row0 = mt * 16 + g;
    const int row1 = row0 + 8;
    __half* usw = us + wid * 16 * SROW;  // this warp's 16x128 tile

    float acc[16][4];
#pragma unroll
    for (int q = 0; q < 16; q++)
#pragma unroll
        for (int r = 0; r < 4; r++) acc[q][r] = 0.f;

    for (int k = 0; k < 16; k++) {
        const int i = ic * 16 + k;

        // A fragment from fp32 x
        const float* xp0 = x + ((size_t)row0 * N_ + i) * 16 + 2 * tg;
        const float* xp1 = x + ((size_t)row1 * N_ + i) * 16 + 2 * tg;
        float2 f0 = *(const float2*)xp0;
        float2 f1 = *(const float2*)xp1;
        float2 f2 = *(const float2*)(xp0 + 8);
        float2 f3 = *(const float2*)(xp1 + 8);
        uint32_t A0 = packh2(f0.x, f0.y);
        uint32_t A1 = packh2(f1.x, f1.y);
        uint32_t A2 = packh2(f2.x, f2.y);
        uint32_t A3 = packh2(f3.x, f3.y);

#pragma unroll
        for (int q = 0; q < 16; q++) {
            const int col = jd0 + q * 8 + g;
            const float* wp = w + ((size_t)i * JD_ + col) * 16 + 2 * tg;
            float2 w0 = *(const float2*)wp;
            float2 w1 = *(const float2*)(wp + 8);
            uint32_t Bb0 = packh2(w0.x, w0.y);
            uint32_t Bb1 = packh2(w1.x, w1.y);

            float d0, d1, d2, d3;
            mma16816(d0, d1, d2, d3, A0, A1, A2, A3, Bb0, Bb1);
            acc[q][0] += d0; acc[q][1] += d1;
            acc[q][2] += d2; acc[q][3] += d3;

            // stage fragments: row-local col q*8+2tg, rows g / g+8
            *(uint32_t*)(usw + g * SROW       + q * 8 + 2 * tg) = packh2(d0, d1);
            *(uint32_t*)(usw + (g + 8) * SROW + q * 8 + 2 * tg) = packh2(d2, d3);
        }
        __syncwarp();

        // coalesced copy-out: 16 rows x 256 B -> u[b][i][jd0..jd0+128)
#pragma unroll
        for (int it = 0; it < 8; it++) {
            const int r   = it * 2 + (lane >> 4);
            const int off = lane & 15;
            uint4 v = *(const uint4*)(usw + r * SROW + off * 8);
            *(uint4*)(g_u + ((size_t)(mt * 16 + r) * N_ + i) * JD_ + jd0 + off * 8) = v;
        }
        __syncwarp();
    }

    // s1 partials: g_part1[ic][b][jd], scaled by 1/32
    float* pb = g_part1 + ((size_t)ic * B_ + row0) * JD_;
    const float cinv = 1.0f / 32.0f;
#pragma unroll
    for (int q = 0; q < 16; q++) {
        const int col = jd0 + q * 8 + 2 * tg;
        *(float2*)(pb + col)           = make_float2(acc[q][0] * cinv, acc[q][1] * cinv);
        *(float2*)(pb + 8 * JD_ + col) = make_float2(acc[q][2] * cinv, acc[q][3] * cinv);
    }
}

// ---------------------------------------------------------------------------
// Stage A of s1 reduce: 128 chunks -> 16 (high parallelism, 524288 threads).
// ---------------------------------------------------------------------------
__global__ void k_red1() {
    const int gidx = blockIdx.x * 256 + threadIdx.x;   // 2048 CTAs * 256
    const int grp  = gidx >> 15;                       // 0..15 (B_*JD_ = 32768)
    const int idx  = gidx & 32767;
    const float* p = g_part1 + (size_t)grp * 8 * (B_ * JD_) + idx;
    float s = 0.f;
#pragma unroll
    for (int c = 0; c < 8; c++)
        s += p[(size_t)c * B_ * JD_];
    g_part2[(size_t)grp * (B_ * JD_) + idx] = s;
}

// ---------------------------------------------------------------------------
// Routing sweep over fp16 u, depth-1 prefetch (round-7 proven), with the
// softmax max-subtraction removed (logits bounded |bl| <~ 5: exp is safe and
// softmax is shift-invariant) and fast division. Halves the serialized
// shuffle chain per iteration.
// Grid (16, 64), 256 thr = 8 warps, warp handles 16 i, lane = j.
// ---------------------------------------------------------------------------
__global__ __launch_bounds__(256, 4) void k_pass(int vIdx) {
    const int b    = blockIdx.y;
    const int ic   = blockIdx.x;
    const int t    = threadIdx.x;
    const int warp = t >> 5;
    const int j    = t & 31;

    __shared__ float vs[JD_];
    __shared__ float ss[8][JD_];

    for (int idx = t; idx < JD_; idx += 256)
        vs[idx] = g_v[vIdx][b * JD_ + idx];
    __syncthreads();

    __half2 vj2[8];
#pragma unroll
    for (int q = 0; q < 8; q++)
        vj2[q] = __floats2half2_rn(vs[j * 16 + 2 * q], vs[j * 16 + 2 * q + 1]);

    float acc[16];
#pragma unroll
    for (int d = 0; d < 16; d++) acc[d] = 0.f;

    const int ibase = ic * 128 + warp * 16;
    const uint4* ub = (const uint4*)(g_u + ((size_t)b * N_ + ibase) * JD_) + j * 2;

    uint4 p0 = __ldcs(ub);
    uint4 p1 = __ldcs(ub + 1);
    for (int k = 0; k < 16; k++) {
        // prefetch next i (clamped; MLP overlap with softmax latency)
        const int kn = (k < 15) ? k + 1 : 15;
        uint4 n0 = __ldcs(ub + (size_t)kn * 64);
        uint4 n1 = __ldcs(ub + (size_t)kn * 64 + 1);

        // logit in half2
        const __half2* u2a = (const __half2*)&p0;
        const __half2* u2b = (const __half2*)&p1;
        __half2 h = __hmul2(u2a[0], vj2[0]);
#pragma unroll
        for (int q = 1; q < 4; q++) h = __hfma2(u2a[q], vj2[q], h);
#pragma unroll
        for (int q = 0; q < 4; q++) h = __hfma2(u2b[q], vj2[4 + q], h);
        float bl = __low2float(h) + __high2float(h);

        // softmax over 32 j-lanes, no max-subtraction (bounded logits)
        float ex = __expf(bl);
        float sum = ex;
#pragma unroll
        for (int o = 16; o > 0; o >>= 1)
            sum += __shfl_xor_sync(0xffffffffu, sum, o);
        const float c = __fdividef(ex, sum);

        // acc += c * u (fp32 unpack)
#pragma unroll
        for (int q = 0; q < 4; q++) {
            float2 ua = __half22float2(u2a[q]);
            float2 uc = __half22float2(u2b[q]);
            acc[2*q]     += c * ua.x;
            acc[2*q+1]   += c * ua.y;
            acc[8+2*q]   += c * uc.x;
            acc[8+2*q+1] += c * uc.y;
        }

        p0 = n0; p1 = n1;
    }

#pragma unroll
    for (int d = 0; d < 16; d++) ss[warp][d * 32 + j] = acc[d];
    __syncthreads();

    for (int idx = t; idx < JD_; idx += 256) {
        int d = idx >> 5, jj = idx & 31;
        float r = 0.f;
#pragma unroll
        for (int wi = 0; wi < 8; wi++) r += ss[wi][idx];
        g_part2[((size_t)ic * B_ + b) * JD_ + jj * 16 + d] = r;
    }
}

// ---------------------------------------------------------------------------
// Reduce g_part2 over 16 chunks, then squash.
// mode 0: g_v[0] = squash_J(s)             (v1)
// mode 1: g_v[1] = squash_J(s) + g_v[0]    (v1 + v2, additive logits)
// mode 2: out    = squash_D(s)
// ---------------------------------------------------------------------------
__global__ void k_squash(int mode, float* __restrict__ out) {
    const int b = blockIdx.x;
    const int t = threadIdx.x;     // t = j*16 + d
    const float* p = g_part2 + (size_t)b * JD_ + t;
    float s = 0.f;
#pragma unroll
    for (int ic = 0; ic < 16; ic++)
        s += p[(size_t)ic * B_ * JD_];

    if (mode == 2) {
        float q = s * s;
#pragma unroll
        for (int o = 1; o < 16; o <<= 1)   // 16 consecutive lanes = same j
            q += __shfl_xor_sync(0xffffffffu, q, o);
        out[b * JD_ + t] = s * (q / (1.f + q)) * rsqrtf(q + EPS_);
        return;
    }

    __shared__ float sq[16];
    if (t < 16) sq[t] = 0.f;
    __syncthreads();
    atomicAdd(&sq[t & 15], s * s);
    __syncthreads();
    float q = sq[t & 15];
    float v = s * (q / (1.f + q)) * rsqrtf(q + EPS_);
    if (mode == 0) g_v[0][b * JD_ + t] = v;
    else           g_v[1][b * JD_ + t] = v + g_v[0][b * JD_ + t];
}

// ---------------------------------------------------------------------------
extern "C" void kernel_launch(void* const* d_in, const int* in_sizes, int n_in,
                              void* d_out, int out_size) {
    const float* x = (const float*)d_in[0];
    const float* w = (const float*)d_in[1];
    if (in_sizes[0] != B_ * N_ * 16) {       // defensive input-order check
        x = (const float*)d_in[1];
        w = (const float*)d_in[0];
    }

    const int smemB = 16 * 16 * SROW * 2;    // 69632 B
    cudaFuncSetAttribute(k_u, cudaFuncAttributeMaxDynamicSharedMemorySize, smemB);

    k_u<<<128, 512, smemB>>>(x, w);              // u fp16 + s1 partials (128 chunks)
    k_red1<<<2048, 256>>>();                     // s1: 128 -> 16 chunks
    k_squash<<<B_, JD_>>>(0, nullptr);           // v1 = squash_J(s1)
    dim3 pg(16, B_);
    k_pass<<<pg, 256>>>(0);                      // iter 2: softmax(u.v1) -> s2
    k_squash<<<B_, JD_>>>(1, nullptr);           // vsum = squash_J(s2) + v1
    k_pass<<<pg, 256>>>(1);                      // final: softmax(u.vsum) -> s3
    k_squash<<<B_, JD_>>>(2, (float*)d_out);     // out = squash_D(s3)
}